// round 1
// baseline (speedup 1.0000x reference)
#include <cuda_runtime.h>
#include <cuda_bf16.h>
#include <cstdint>

// ---------------------------------------------------------------------------
// INT8Linear: per-token/per-channel int8 quantized GEMM, emulated exactly with
// bf16 tensor cores (int8 values are exact in bf16; K=1024 partial sums of
// integer products stay < 2^24 so fp32 accumulation is exact).
// Inputs:  d_in[0] = x      (8*4096*1024 fp32)
//          d_in[1] = weight (1024*1024   fp32)
//          d_in[2] = bias   (1024        fp32)
// Output:  fp32 (8*4096*1024)
// ---------------------------------------------------------------------------

static constexpr int DIN   = 1024;
static constexpr int DOUT  = 1024;
static constexpr int MAX_M = 32768;

// Scratch (device globals: allocation-free per harness rules)
__device__ __nv_bfloat16 g_Xq[(size_t)MAX_M * DIN];   // 64 MB
__device__ __nv_bfloat16 g_Wq[(size_t)DOUT  * DIN];   //  2 MB
__device__ float         g_xs[MAX_M];
__device__ float         g_ws[DOUT];

// ---------------------------------------------------------------------------
// Row quantizer: one block per row of 1024 floats. 256 threads, 1 float4 each.
// scale = max(amax, 1e-8) / 127 ; q = clip(rint(v/scale), -128, 127) -> bf16
// ---------------------------------------------------------------------------
__device__ __forceinline__ void quant_row(const float* __restrict__ src,
                                          __nv_bfloat16* __restrict__ dq,
                                          float* __restrict__ ds) {
    const int row = blockIdx.x;
    const int t   = threadIdx.x;  // 256 threads

    const float4 v = reinterpret_cast<const float4*>(src + (size_t)row * 1024)[t];
    float am = fmaxf(fmaxf(fabsf(v.x), fabsf(v.y)), fmaxf(fabsf(v.z), fabsf(v.w)));

    #pragma unroll
    for (int o = 16; o > 0; o >>= 1)
        am = fmaxf(am, __shfl_xor_sync(0xffffffffu, am, o));

    __shared__ float red[8];
    if ((t & 31) == 0) red[t >> 5] = am;
    __syncthreads();
    if (t < 32) {
        float r = (t < 8) ? red[t] : 0.0f;
        #pragma unroll
        for (int o = 4; o > 0; o >>= 1)
            r = fmaxf(r, __shfl_xor_sync(0xffffffffu, r, o));
        if (t == 0) red[0] = r;
    }
    __syncthreads();

    const float amax  = fmaxf(red[0], 1e-8f);
    const float scale = amax / 127.0f;
    if (t == 0) ds[row] = scale;

    float q0 = fminf(fmaxf(rintf(v.x / scale), -128.0f), 127.0f);
    float q1 = fminf(fmaxf(rintf(v.y / scale), -128.0f), 127.0f);
    float q2 = fminf(fmaxf(rintf(v.z / scale), -128.0f), 127.0f);
    float q3 = fminf(fmaxf(rintf(v.w / scale), -128.0f), 127.0f);

    __nv_bfloat162 p0 = __floats2bfloat162_rn(q0, q1);
    __nv_bfloat162 p1 = __floats2bfloat162_rn(q2, q3);
    uint2 pk;
    pk.x = *reinterpret_cast<uint32_t*>(&p0);
    pk.y = *reinterpret_cast<uint32_t*>(&p1);
    *reinterpret_cast<uint2*>(dq + (size_t)row * 1024 + t * 4) = pk;
}

__global__ void quant_x_kernel(const float* __restrict__ x) {
    quant_row(x, g_Xq, g_xs);
}
__global__ void quant_w_kernel(const float* __restrict__ w) {
    quant_row(w, g_Wq, g_ws);
}

// ---------------------------------------------------------------------------
// GEMM: out[m][n] = (sum_k Xq[m][k]*Wq[n][k]) * xs[m] * ws[n] + bias[n]
// Block tile 128x128, K-tile 64. 256 threads = 8 warps (2 M x 4 N),
// warp tile 64x32 = 4x4 mma.m16n8k16 fragments.
// ---------------------------------------------------------------------------
#define BM 128
#define BN 128
#define BK 64
#define KPAD 8   // pad to 72 bf16 = 144B row stride (16B aligned, conflict-free)

__global__ __launch_bounds__(256, 2)
void gemm_bf16_kernel(const float* __restrict__ bias, float* __restrict__ out) {
    __shared__ __align__(16) __nv_bfloat16 As[BM][BK + KPAD];
    __shared__ __align__(16) __nv_bfloat16 Bs[BN][BK + KPAD];

    const int bm   = blockIdx.y * BM;
    const int bn   = blockIdx.x * BN;
    const int tid  = threadIdx.x;
    const int warp = tid >> 5;
    const int lane = tid & 31;
    const int wm   = (warp & 1) * 64;   // warp M offset in tile
    const int wn   = (warp >> 1) * 32;  // warp N offset in tile

    float acc[4][4][4];
    #pragma unroll
    for (int im = 0; im < 4; im++)
        #pragma unroll
        for (int in_ = 0; in_ < 4; in_++)
            #pragma unroll
            for (int r = 0; r < 4; r++) acc[im][in_][r] = 0.0f;

    for (int kt = 0; kt < DIN / BK; kt++) {
        const int k0 = kt * BK;
        // Load 128x64 bf16 tiles: 1024 uint4 vectors per tile, 4 per thread.
        #pragma unroll
        for (int i = 0; i < 4; i++) {
            const int v = tid + 256 * i;
            const int r = v >> 3;
            const int c = (v & 7) * 8;
            *reinterpret_cast<uint4*>(&As[r][c]) =
                *reinterpret_cast<const uint4*>(&g_Xq[(size_t)(bm + r) * DIN + k0 + c]);
            *reinterpret_cast<uint4*>(&Bs[r][c]) =
                *reinterpret_cast<const uint4*>(&g_Wq[(size_t)(bn + r) * DIN + k0 + c]);
        }
        __syncthreads();

        #pragma unroll
        for (int ks = 0; ks < BK / 16; ks++) {
            const int k = ks * 16;
            uint32_t a[4][4], b[4][2];

            #pragma unroll
            for (int im = 0; im < 4; im++) {
                const int r = wm + im * 16 + (lane & 15);
                const int c = k + (lane >> 4) * 8;
                uint32_t addr = (uint32_t)__cvta_generic_to_shared(&As[r][c]);
                asm volatile(
                    "ldmatrix.sync.aligned.m8n8.x4.shared.b16 {%0,%1,%2,%3}, [%4];"
                    : "=r"(a[im][0]), "=r"(a[im][1]), "=r"(a[im][2]), "=r"(a[im][3])
                    : "r"(addr));
            }
            #pragma unroll
            for (int in_ = 0; in_ < 4; in_++) {
                const int l16 = lane & 15;
                const int r = wn + in_ * 8 + (l16 & 7);
                const int c = k + (l16 >> 3) * 8;
                uint32_t addr = (uint32_t)__cvta_generic_to_shared(&Bs[r][c]);
                asm volatile(
                    "ldmatrix.sync.aligned.m8n8.x2.shared.b16 {%0,%1}, [%2];"
                    : "=r"(b[in_][0]), "=r"(b[in_][1])
                    : "r"(addr));
            }
            #pragma unroll
            for (int im = 0; im < 4; im++) {
                #pragma unroll
                for (int in_ = 0; in_ < 4; in_++) {
                    asm volatile(
                        "mma.sync.aligned.m16n8k16.row.col.f32.bf16.bf16.f32 "
                        "{%0,%1,%2,%3}, {%4,%5,%6,%7}, {%8,%9}, {%0,%1,%2,%3};"
                        : "+f"(acc[im][in_][0]), "+f"(acc[im][in_][1]),
                          "+f"(acc[im][in_][2]), "+f"(acc[im][in_][3])
                        : "r"(a[im][0]), "r"(a[im][1]), "r"(a[im][2]), "r"(a[im][3]),
                          "r"(b[in_][0]), "r"(b[in_][1]));
                }
            }
        }
        __syncthreads();
    }

    // Epilogue: dequant + bias. c0/c1 -> (row, col), (row, col+1); c2/c3 -> row+8.
    #pragma unroll
    for (int im = 0; im < 4; im++) {
        const int row0 = bm + wm + im * 16 + (lane >> 2);
        const float xs0 = g_xs[row0];
        const float xs8 = g_xs[row0 + 8];
        #pragma unroll
        for (int in_ = 0; in_ < 4; in_++) {
            const int col = bn + wn + in_ * 8 + (lane & 3) * 2;
            const float ws0 = g_ws[col],  ws1 = g_ws[col + 1];
            const float bb0 = bias[col],  bb1 = bias[col + 1];

            float2 o0, o1;
            o0.x = acc[im][in_][0] * xs0 * ws0 + bb0;
            o0.y = acc[im][in_][1] * xs0 * ws1 + bb1;
            o1.x = acc[im][in_][2] * xs8 * ws0 + bb0;
            o1.y = acc[im][in_][3] * xs8 * ws1 + bb1;
            *reinterpret_cast<float2*>(out + (size_t)row0 * DOUT + col)       = o0;
            *reinterpret_cast<float2*>(out + (size_t)(row0 + 8) * DOUT + col) = o1;
        }
    }
}

// ---------------------------------------------------------------------------
extern "C" void kernel_launch(void* const* d_in, const int* in_sizes, int n_in,
                              void* d_out, int out_size) {
    const float* x    = (const float*)d_in[0];
    const float* w    = (const float*)d_in[1];
    const float* bias = (const float*)d_in[2];
    float* out        = (float*)d_out;

    const int M = in_sizes[0] / DIN;  // 32768

    quant_w_kernel<<<DOUT, 256>>>(w);
    quant_x_kernel<<<M, 256>>>(x);

    dim3 grid(DOUT / BN, M / BM);  // (8, 256)
    gemm_bf16_kernel<<<grid, 256>>>(bias, out);
}